// round 15
// baseline (speedup 1.0000x reference)
#include <cuda_runtime.h>

// Fixed-shape problem: logits [8,19,512,512] f32, target [8,512,512] (int32 on device)
#define NCLS 19
#define HW   262144           // 512*512
#define HW2  131072           // float2 pairs per plane
#define CHW  (NCLS * HW)
#define NBLK 444              // 3 CTAs per SM
#define NTHR 256
#define QMUL 1024.0f          // s_iq = 1024*count + sum(pt); per-block count < 1024

// Per-block partials: [0..18]=prob_sums, [19..37]=iq packed, [57]=anll, [58]=afoc
__device__ float    g_part[NBLK][64];
__device__ unsigned g_sem;     // zero-initialized; self-resetting

__device__ __forceinline__ float ex2f(float x){ float r; asm("ex2.approx.ftz.f32 %0,%1;":"=f"(r):"f"(x)); return r; }
__device__ __forceinline__ float lg2f(float x){ float r; asm("lg2.approx.ftz.f32 %0,%1;":"=f"(r):"f"(x)); return r; }
__device__ __forceinline__ float rcpf(float x){ float r; asm("rcp.approx.ftz.f32 %0,%1;":"=f"(r):"f"(x)); return r; }
__device__ __forceinline__ void  pfL2(const void* p){ asm volatile("prefetch.global.L2 [%0];" :: "l"(p)); }

#define L2E 1.44269504088896f
#define LN2 0.69314718055995f

__global__ void __launch_bounds__(NTHR, 3)      // 24 warps/SM, <=85 regs, ~79 live
fdl_kernel(const float* __restrict__ logits,
           const int*   __restrict__ target,
           const float* __restrict__ cw,
           const float* __restrict__ fa,
           float*       __restrict__ out,
           int P2)
{
    __shared__ float s_cw[NCLS], s_fa[NCLS];
    __shared__ float s_iq[NCLS];                 // per-CTA packed intersection/count
    __shared__ float s_red[64];
    __shared__ float s_fin[4][64];
    __shared__ bool  s_last;

    const int tid = threadIdx.x;
    if (tid < NCLS) { s_cw[tid] = cw[tid]; s_fa[tid] = fa[tid]; s_iq[tid] = 0.f; }
    if (tid < 64)   s_red[tid] = 0.f;
    __syncthreads();

    float ps[NCLS];
#pragma unroll
    for (int c = 0; c < NCLS; ++c) ps[c] = 0.f;
    float anll = 0.f, afoc = 0.f;

    const int  stride = NBLK * NTHR;             // 113664 pixel-pairs
    const bool pflane = ((tid & 15) == 0);       // lanes 0/16: one 128B line each

    int pp  = blockIdx.x * NTHR + tid;           // pixel-pair index; < P2 on entry
    int2 t2 = __ldg((const int2*)target + pp);   // target pipeline (2 regs only)

    for (;;) {
        const int  next = pp + stride;
        const bool more = (next < P2);           // warp-uniform

        const int b  = pp >> 17;
        const int hw = pp & (HW2 - 1);
        const float2* basep = (const float2*)(logits + (size_t)b * CHW) + hw;

        // Distance-1 L2 prefetch for the NEXT iteration (issued first; the per-warp
        // iteration wall time >> DRAM latency, so next iter's LDGs become L2 hits).
        if (pflane & more) {
            const int nb  = next >> 17;
            const int nhw = next & (HW2 - 1);
            const float2* np = (const float2*)(logits + (size_t)nb * CHW) + nhw;
#pragma unroll
            for (int c = 0; c < NCLS; ++c) pfL2(np + (size_t)c * HW2);
            pfL2((const int2*)target + next);
        }

        // Direct loads (L2 hits thanks to last iteration's prefetch)
        float2 l[NCLS];
#pragma unroll
        for (int c = 0; c < NCLS; ++c) l[c] = __ldg(basep + (size_t)c * HW2);

        // Target-class logits: gathers hit the same lines (MSHR/L1 coalesced)
        const float yt0 = __ldg(basep + (size_t)t2.x * HW2).x;
        const float yt1 = __ldg(basep + (size_t)t2.y * HW2).y;
        const int   tt0 = t2.x, tt1 = t2.y;

        // Next iteration's target (tiny, fully hidden)
        if (more) t2 = __ldg((const int2*)target + next);

        // In-place exp2: l[] becomes e[] (no separate ex/ey arrays -> low reg count)
        float Sx = 0.f, Sy = 0.f;
#pragma unroll
        for (int c = 0; c < NCLS; ++c) {
            l[c].x = ex2f(l[c].x * L2E);  Sx += l[c].x;
            l[c].y = ex2f(l[c].y * L2E);  Sy += l[c].y;
        }
        const float invSx = rcpf(Sx);
        const float invSy = rcpf(Sy);

        // Pixel 0
        {
            const float d      = fmaf(yt0, L2E, -lg2f(Sx));
            const float log_pt = d * LN2;
            const float pt     = ex2f(d);
            anll = fmaf(s_cw[tt0], log_pt, anll);
            const float om = 1.f - fmaxf(pt, 1e-8f);
            afoc = fmaf(s_fa[tt0] * om * om, log_pt, afoc);
            atomicAdd(&s_iq[tt0], pt + QMUL);
        }
        // Pixel 1
        {
            const float d      = fmaf(yt1, L2E, -lg2f(Sy));
            const float log_pt = d * LN2;
            const float pt     = ex2f(d);
            anll = fmaf(s_cw[tt1], log_pt, anll);
            const float om = 1.f - fmaxf(pt, 1e-8f);
            afoc = fmaf(s_fa[tt1] * om * om, log_pt, afoc);
            atomicAdd(&s_iq[tt1], pt + QMUL);
        }

#pragma unroll
        for (int c = 0; c < NCLS; ++c)
            ps[c] = fmaf(l[c].x, invSx, fmaf(l[c].y, invSy, ps[c]));

        if (!more) break;
        pp = next;
    }

    // ---- Block reduction ----
    const unsigned full = 0xffffffffu;
    const bool lead = ((tid & 31) == 0);
#pragma unroll
    for (int c = 0; c < NCLS; ++c) {
        float v0 = ps[c];
#pragma unroll
        for (int o = 16; o > 0; o >>= 1) v0 += __shfl_down_sync(full, v0, o);
        if (lead) atomicAdd(&s_red[c], v0);
    }
    {
        float v0 = anll, v1 = afoc;
#pragma unroll
        for (int o = 16; o > 0; o >>= 1) {
            v0 += __shfl_down_sync(full, v0, o);
            v1 += __shfl_down_sync(full, v1, o);
        }
        if (lead) {
            atomicAdd(&s_red[57], v0);
            atomicAdd(&s_red[58], v1);
        }
    }
    __syncthreads();

    if (tid < NCLS) s_red[NCLS + tid] = s_iq[tid];   // iq packed -> slots 19..37
    __syncthreads();
    if (tid < 64) g_part[blockIdx.x][tid] = s_red[tid];

    // ---- Last block performs the final reduction (deterministic order) ----
    __threadfence();
    if (tid == 0) s_last = (atomicAdd(&g_sem, 1u) == NBLK - 1);
    __syncthreads();
    if (!s_last) return;

    if (tid == 0) g_sem = 0;    // reset for next graph replay
    __threadfence();

    {
        const int v = tid & 63;
        const int slice = tid >> 6;          // 0..3
        if (v < NCLS || v >= 57) {           // plain sums: ps + scalars
            float acc = 0.f;
            for (int bb = slice; bb < NBLK; bb += 4) acc += g_part[bb][v];
            s_fin[slice][v] = acc;
        } else if (v < 2 * NCLS) {           // iq: unpack PER BLOCK, then sum
            float ai = 0.f, ac = 0.f;
            for (int bb = slice; bb < NBLK; bb += 4) {
                const float q  = g_part[bb][v];
                const float cf = floorf(q * (1.0f / QMUL));   // exact block count
                ai += q - QMUL * cf;
                ac += cf;
            }
            s_fin[slice][v]        = ai;     // intersection -> 19..37
            s_fin[slice][v + NCLS] = ac;     // counts       -> 38..56
        }
    }
    __syncthreads();
    if (tid < 64)
        s_fin[0][tid] = s_fin[0][tid] + s_fin[1][tid] + s_fin[2][tid] + s_fin[3][tid];
    __syncthreads();

    if (tid == 0) {
        const float Pf = (float)P2 * 2.0f;
        float swt = 0.f;                      // sum w_t from per-class counts
#pragma unroll
        for (int c = 0; c < NCLS; ++c) swt = fmaf(s_fin[0][2 * NCLS + c], s_cw[c], swt);

        const float ce    = -s_fin[0][57] / swt;
        const float focal = -s_fin[0][58] / Pf;

        float sw = 0.f;
#pragma unroll
        for (int c = 0; c < NCLS; ++c) sw += s_cw[c];
        sw = fmaxf(sw, 1e-8f);

        float dsum = 0.f;
#pragma unroll
        for (int c = 0; c < NCLS; ++c) {
            const float dice = (2.f * s_fin[0][NCLS + c] + 1.f)
                             / (s_fin[0][c] + s_fin[0][2 * NCLS + c] + 1.f);
            dsum += dice * (s_cw[c] / sw);
        }
        const float dice_loss = 1.f - dsum;
        out[0] = 0.4f * ce + 0.3f * focal + 0.3f * dice_loss;
    }
}

extern "C" void kernel_launch(void* const* d_in, const int* in_sizes, int n_in,
                              void* d_out, int out_size)
{
    const float* logits = (const float*)d_in[0];
    const int*   target = (const int*)d_in[1];
    const float* cw     = (const float*)d_in[2];
    const float* fa     = (const float*)d_in[3];
    float*       out    = (float*)d_out;

    const int P2 = in_sizes[1] / 2;   // 1,048,576 pixel-pairs

    fdl_kernel<<<NBLK, NTHR>>>(logits, target, cw, fa, out, P2);
}

// round 16
// speedup vs baseline: 1.0194x; 1.0194x over previous
#include <cuda_runtime.h>

// Fixed-shape problem: logits [8,19,512,512] f32, target [8,512,512] (int32 on device)
#define NCLS 19
#define HW   262144           // 512*512
#define HW2  131072           // float2 pairs per plane
#define CHW  (NCLS * HW)
#define NBLK 444              // 3 CTAs per SM
#define NTHR 256
#define QMUL 1024.0f          // s_iq = 1024*count + sum(pt); per-block count < 1024

// Per-block partials: [0..18]=prob_sums, [19..37]=iq packed, [57]=anll, [58]=afoc
__device__ float    g_part[NBLK][64];
__device__ unsigned g_sem;     // zero-initialized; self-resetting

__device__ __forceinline__ float ex2f(float x){ float r; asm("ex2.approx.ftz.f32 %0,%1;":"=f"(r):"f"(x)); return r; }
__device__ __forceinline__ float lg2f(float x){ float r; asm("lg2.approx.ftz.f32 %0,%1;":"=f"(r):"f"(x)); return r; }
__device__ __forceinline__ float rcpf(float x){ float r; asm("rcp.approx.ftz.f32 %0,%1;":"=f"(r):"f"(x)); return r; }

#define L2E 1.44269504088896f
#define LN2 0.69314718055995f

__global__ void __launch_bounds__(NTHR, 3)      // 24 warps/SM, <=85 regs, ~80 live
fdl_kernel(const float* __restrict__ logits,
           const int*   __restrict__ target,
           const float* __restrict__ cw,
           const float* __restrict__ fa,
           float*       __restrict__ out,
           int P2)
{
    __shared__ float s_cw[NCLS], s_fa[NCLS];
    __shared__ float s_iq[NCLS];                 // per-CTA packed intersection/count
    __shared__ float s_red[64];
    __shared__ float s_fin[4][64];
    __shared__ bool  s_last;

    const int tid = threadIdx.x;
    if (tid < NCLS) { s_cw[tid] = cw[tid]; s_fa[tid] = fa[tid]; s_iq[tid] = 0.f; }
    if (tid < 64)   s_red[tid] = 0.f;
    __syncthreads();

    float ps[NCLS];
#pragma unroll
    for (int c = 0; c < NCLS; ++c) ps[c] = 0.f;
    float anll = 0.f, afoc = 0.f;

    const int stride = NBLK * NTHR;              // 113664 pixel-pairs

    int pp  = blockIdx.x * NTHR + tid;           // pixel-pair index; < P2 on entry
    int2 t2 = __ldg((const int2*)target + pp);   // target pipeline (2 regs only)

    for (;;) {
        const int  next = pp + stride;
        const bool more = (next < P2);           // warp-uniform

        const int b  = pp >> 17;
        const int hw = pp & (HW2 - 1);
        const float2* basep = (const float2*)(logits + (size_t)b * CHW) + hw;

        // 19 payload streams only — minimal L1tex wavefronts (0.61 lines/px).
        // MLP (19 LDG.64 x 24 warps/SM) covers DRAM latency without prefetch.
        float2 l[NCLS];
#pragma unroll
        for (int c = 0; c < NCLS; ++c) l[c] = __ldg(basep + (size_t)c * HW2);

        const int tt0 = t2.x, tt1 = t2.y;
        if (more) t2 = __ldg((const int2*)target + next);

        // In-place exp2: l[] becomes e[]
        float Sx = 0.f, Sy = 0.f;
#pragma unroll
        for (int c = 0; c < NCLS; ++c) {
            l[c].x = ex2f(l[c].x * L2E);  Sx += l[c].x;
            l[c].y = ex2f(l[c].y * L2E);  Sy += l[c].y;
        }

        // Target-class exp via select chains (alu pipe — measured 4.8% busy)
        float et0 = l[0].x, et1 = l[0].y;
#pragma unroll
        for (int c = 1; c < NCLS; ++c) {
            et0 = (tt0 == c) ? l[c].x : et0;
            et1 = (tt1 == c) ? l[c].y : et1;
        }

        const float invSx = rcpf(Sx);
        const float invSy = rcpf(Sy);

        // Pixel 0
        {
            const float pt     = et0 * invSx;
            const float log_pt = lg2f(pt) * LN2;
            anll = fmaf(s_cw[tt0], log_pt, anll);
            const float om = 1.f - fmaxf(pt, 1e-8f);
            afoc = fmaf(s_fa[tt0] * om * om, log_pt, afoc);
            atomicAdd(&s_iq[tt0], pt + QMUL);
        }
        // Pixel 1
        {
            const float pt     = et1 * invSy;
            const float log_pt = lg2f(pt) * LN2;
            anll = fmaf(s_cw[tt1], log_pt, anll);
            const float om = 1.f - fmaxf(pt, 1e-8f);
            afoc = fmaf(s_fa[tt1] * om * om, log_pt, afoc);
            atomicAdd(&s_iq[tt1], pt + QMUL);
        }

#pragma unroll
        for (int c = 0; c < NCLS; ++c)
            ps[c] = fmaf(l[c].x, invSx, fmaf(l[c].y, invSy, ps[c]));

        if (!more) break;
        pp = next;
    }

    // ---- Block reduction ----
    const unsigned full = 0xffffffffu;
    const bool lead = ((tid & 31) == 0);
#pragma unroll
    for (int c = 0; c < NCLS; ++c) {
        float v0 = ps[c];
#pragma unroll
        for (int o = 16; o > 0; o >>= 1) v0 += __shfl_down_sync(full, v0, o);
        if (lead) atomicAdd(&s_red[c], v0);
    }
    {
        float v0 = anll, v1 = afoc;
#pragma unroll
        for (int o = 16; o > 0; o >>= 1) {
            v0 += __shfl_down_sync(full, v0, o);
            v1 += __shfl_down_sync(full, v1, o);
        }
        if (lead) {
            atomicAdd(&s_red[57], v0);
            atomicAdd(&s_red[58], v1);
        }
    }
    __syncthreads();

    if (tid < NCLS) s_red[NCLS + tid] = s_iq[tid];   // iq packed -> slots 19..37
    __syncthreads();
    if (tid < 64) g_part[blockIdx.x][tid] = s_red[tid];

    // ---- Last block performs the final reduction (deterministic order) ----
    __threadfence();
    if (tid == 0) s_last = (atomicAdd(&g_sem, 1u) == NBLK - 1);
    __syncthreads();
    if (!s_last) return;

    if (tid == 0) g_sem = 0;    // reset for next graph replay
    __threadfence();

    {
        const int v = tid & 63;
        const int slice = tid >> 6;          // 0..3
        if (v < NCLS || v >= 57) {           // plain sums: ps + scalars
            float acc = 0.f;
            for (int bb = slice; bb < NBLK; bb += 4) acc += g_part[bb][v];
            s_fin[slice][v] = acc;
        } else if (v < 2 * NCLS) {           // iq: unpack PER BLOCK, then sum
            float ai = 0.f, ac = 0.f;
            for (int bb = slice; bb < NBLK; bb += 4) {
                const float q  = g_part[bb][v];
                const float cf = floorf(q * (1.0f / QMUL));   // exact block count
                ai += q - QMUL * cf;
                ac += cf;
            }
            s_fin[slice][v]        = ai;     // intersection -> 19..37
            s_fin[slice][v + NCLS] = ac;     // counts       -> 38..56
        }
    }
    __syncthreads();
    if (tid < 64)
        s_fin[0][tid] = s_fin[0][tid] + s_fin[1][tid] + s_fin[2][tid] + s_fin[3][tid];
    __syncthreads();

    if (tid == 0) {
        const float Pf = (float)P2 * 2.0f;
        float swt = 0.f;                      // sum w_t from per-class counts
#pragma unroll
        for (int c = 0; c < NCLS; ++c) swt = fmaf(s_fin[0][2 * NCLS + c], s_cw[c], swt);

        const float ce    = -s_fin[0][57] / swt;
        const float focal = -s_fin[0][58] / Pf;

        float sw = 0.f;
#pragma unroll
        for (int c = 0; c < NCLS; ++c) sw += s_cw[c];
        sw = fmaxf(sw, 1e-8f);

        float dsum = 0.f;
#pragma unroll
        for (int c = 0; c < NCLS; ++c) {
            const float dice = (2.f * s_fin[0][NCLS + c] + 1.f)
                             / (s_fin[0][c] + s_fin[0][2 * NCLS + c] + 1.f);
            dsum += dice * (s_cw[c] / sw);
        }
        const float dice_loss = 1.f - dsum;
        out[0] = 0.4f * ce + 0.3f * focal + 0.3f * dice_loss;
    }
}

extern "C" void kernel_launch(void* const* d_in, const int* in_sizes, int n_in,
                              void* d_out, int out_size)
{
    const float* logits = (const float*)d_in[0];
    const int*   target = (const int*)d_in[1];
    const float* cw     = (const float*)d_in[2];
    const float* fa     = (const float*)d_in[3];
    float*       out    = (float*)d_out;

    const int P2 = in_sizes[1] / 2;   // 1,048,576 pixel-pairs

    fdl_kernel<<<NBLK, NTHR>>>(logits, target, cw, fa, out, P2);
}

// round 17
// speedup vs baseline: 1.2102x; 1.1872x over previous
#include <cuda_runtime.h>

// Fixed-shape problem: logits [8,19,512,512] f32, target [8,512,512] (int32 on device)
#define NCLS 19
#define HW   262144           // 512*512
#define HW2  131072           // float2 pairs per plane
#define CHW  (NCLS * HW)
#define NBLK 444              // 3 CTAs per SM
#define NTHR 256
#define NWRP (NTHR / 32)
#define QMUL 1024.0f          // iq = 1024*count + sum(pt); per-block count < 1024

// Global accumulators: [0..18]=prob_sums, [19..37]=intersection, [38..56]=counts,
// [57]=anll, [58]=afoc. Zero at start; last block resets after finalize.
__device__ float    g_acc[64];
__device__ unsigned g_sem;     // zero-initialized; self-resetting

__device__ __forceinline__ float ex2f(float x){ float r; asm("ex2.approx.ftz.f32 %0,%1;":"=f"(r):"f"(x)); return r; }
__device__ __forceinline__ float lg2f(float x){ float r; asm("lg2.approx.ftz.f32 %0,%1;":"=f"(r):"f"(x)); return r; }
__device__ __forceinline__ float rcpf(float x){ float r; asm("rcp.approx.ftz.f32 %0,%1;":"=f"(r):"f"(x)); return r; }

#define L2E 1.44269504088896f
#define LN2 0.69314718055995f

__global__ void __launch_bounds__(NTHR, 3)      // 24 warps/SM, <=85 regs
fdl_kernel(const float* __restrict__ logits,
           const int*   __restrict__ target,
           const float* __restrict__ cw,
           const float* __restrict__ fa,
           float*       __restrict__ out,
           int P2)
{
    __shared__ float s_cw[NCLS], s_fa[NCLS];
    __shared__ float s_iq[NWRP][NCLS];           // per-WARP rows: no cross-warp ATOMS
    __shared__ float s_red[64];
    __shared__ bool  s_last;

    const int tid = threadIdx.x;
    const int wid = tid >> 5;
    if (tid < NCLS) { s_cw[tid] = cw[tid]; s_fa[tid] = fa[tid]; }
    for (int i = tid; i < NWRP * NCLS; i += NTHR) (&s_iq[0][0])[i] = 0.f;
    if (tid < 64) s_red[tid] = 0.f;
    __syncthreads();

    float ps[NCLS];
#pragma unroll
    for (int c = 0; c < NCLS; ++c) ps[c] = 0.f;
    float anll = 0.f, afoc = 0.f;

    const int stride = NBLK * NTHR;              // 113664 pixel-pairs

    int pp  = blockIdx.x * NTHR + tid;           // pixel-pair index; < P2 on entry
    int2 t2 = __ldg((const int2*)target + pp);   // target pipeline (2 regs only)

    for (;;) {
        const int  next = pp + stride;
        const bool more = (next < P2);           // warp-uniform

        const int b  = pp >> 17;
        const int hw = pp & (HW2 - 1);
        const float2* basep = (const float2*)(logits + (size_t)b * CHW) + hw;

        // 19 payload streams — minimal L1tex wavefronts; MLP covers DRAM latency.
        float2 l[NCLS];
#pragma unroll
        for (int c = 0; c < NCLS; ++c) l[c] = __ldg(basep + (size_t)c * HW2);

        const int tt0 = t2.x, tt1 = t2.y;
        if (more) t2 = __ldg((const int2*)target + next);

        // In-place exp2: l[] becomes e[]
        float Sx = 0.f, Sy = 0.f;
#pragma unroll
        for (int c = 0; c < NCLS; ++c) {
            l[c].x = ex2f(l[c].x * L2E);  Sx += l[c].x;
            l[c].y = ex2f(l[c].y * L2E);  Sy += l[c].y;
        }

        // Target-class exp via select chains (alu pipe has headroom)
        float et0 = l[0].x, et1 = l[0].y;
#pragma unroll
        for (int c = 1; c < NCLS; ++c) {
            et0 = (tt0 == c) ? l[c].x : et0;
            et1 = (tt1 == c) ? l[c].y : et1;
        }

        const float invSx = rcpf(Sx);
        const float invSy = rcpf(Sy);

        // Pixel 0
        {
            const float pt     = et0 * invSx;
            const float log_pt = lg2f(pt) * LN2;
            anll = fmaf(s_cw[tt0], log_pt, anll);
            const float om = 1.f - fmaxf(pt, 1e-8f);
            afoc = fmaf(s_fa[tt0] * om * om, log_pt, afoc);
            atomicAdd(&s_iq[wid][tt0], pt + QMUL);
        }
        // Pixel 1
        {
            const float pt     = et1 * invSy;
            const float log_pt = lg2f(pt) * LN2;
            anll = fmaf(s_cw[tt1], log_pt, anll);
            const float om = 1.f - fmaxf(pt, 1e-8f);
            afoc = fmaf(s_fa[tt1] * om * om, log_pt, afoc);
            atomicAdd(&s_iq[wid][tt1], pt + QMUL);
        }

#pragma unroll
        for (int c = 0; c < NCLS; ++c)
            ps[c] = fmaf(l[c].x, invSx, fmaf(l[c].y, invSy, ps[c]));

        if (!more) break;
        pp = next;
    }

    // ---- Block reduction ----
    const unsigned full = 0xffffffffu;
    const bool lead = ((tid & 31) == 0);
#pragma unroll
    for (int c = 0; c < NCLS; ++c) {
        float v0 = ps[c];
#pragma unroll
        for (int o = 16; o > 0; o >>= 1) v0 += __shfl_down_sync(full, v0, o);
        if (lead) atomicAdd(&s_red[c], v0);
    }
    {
        float v0 = anll, v1 = afoc;
#pragma unroll
        for (int o = 16; o > 0; o >>= 1) {
            v0 += __shfl_down_sync(full, v0, o);
            v1 += __shfl_down_sync(full, v1, o);
        }
        if (lead) {
            atomicAdd(&s_red[57], v0);
            atomicAdd(&s_red[58], v1);
        }
    }
    __syncthreads();

    // ---- Straight-to-global accumulation (unpack iq per block first) ----
    if (tid < NCLS) {
        float q = 0.f;
#pragma unroll
        for (int w = 0; w < NWRP; ++w) q += s_iq[w][tid];
        const float cf = floorf(q * (1.0f / QMUL));      // exact per-block count
        atomicAdd(&g_acc[tid],            s_red[tid]);   // prob_sums
        atomicAdd(&g_acc[NCLS + tid],     q - QMUL * cf);// intersection
        atomicAdd(&g_acc[2 * NCLS + tid], cf);           // counts
    } else if (tid == 57 || tid == 58) {
        atomicAdd(&g_acc[tid], s_red[tid]);
    }

    // ---- Last block finalizes (reads 64 floats, not 444x64) ----
    __threadfence();
    if (tid == 0) s_last = (atomicAdd(&g_sem, 1u) == NBLK - 1);
    __syncthreads();
    if (!s_last) return;

    if (tid < 64) s_red[tid] = g_acc[tid];
    __syncthreads();

    if (tid == 0) {
        const float Pf = (float)P2 * 2.0f;
        float swt = 0.f;                      // sum w_t from per-class counts
#pragma unroll
        for (int c = 0; c < NCLS; ++c) swt = fmaf(s_red[2 * NCLS + c], s_cw[c], swt);

        const float ce    = -s_red[57] / swt;
        const float focal = -s_red[58] / Pf;

        float sw = 0.f;
#pragma unroll
        for (int c = 0; c < NCLS; ++c) sw += s_cw[c];
        sw = fmaxf(sw, 1e-8f);

        float dsum = 0.f;
#pragma unroll
        for (int c = 0; c < NCLS; ++c) {
            const float dice = (2.f * s_red[NCLS + c] + 1.f)
                             / (s_red[c] + s_red[2 * NCLS + c] + 1.f);
            dsum += dice * (s_cw[c] / sw);
        }
        const float dice_loss = 1.f - dsum;
        out[0] = 0.4f * ce + 0.3f * focal + 0.3f * dice_loss;
    }

    // Reset global state for the next graph replay (only last block runs here)
    if (tid < 64) g_acc[tid] = 0.f;
    if (tid == 0) g_sem = 0;
}

extern "C" void kernel_launch(void* const* d_in, const int* in_sizes, int n_in,
                              void* d_out, int out_size)
{
    const float* logits = (const float*)d_in[0];
    const int*   target = (const int*)d_in[1];
    const float* cw     = (const float*)d_in[2];
    const float* fa     = (const float*)d_in[3];
    float*       out    = (float*)d_out;

    const int P2 = in_sizes[1] / 2;   // 1,048,576 pixel-pairs

    fdl_kernel<<<NBLK, NTHR>>>(logits, target, cw, fa, out, P2);
}